// round 13
// baseline (speedup 1.0000x reference)
#include <cuda_runtime.h>
#include <math.h>
#include <stdint.h>

#define NN 512
#define MM 2048
#define FEAT 1024
#define GG 16
#define DG 64
#define NSPLIT 4

// ---------------- scratch (device globals; no allocation) ----------------
// d_q/d_k are k-permuted: within each 8-float k-group, stored pos p(k)=(k&3)*2+(k>>2),
// i.e. storage order {0,4,1,5,2,6,3,7}. d_v is PLAIN layout.
__device__ __align__(16) float d_q[NN * FEAT];
__device__ __align__(16) float d_k[MM * FEAT];
__device__ __align__(16) float d_v[MM * FEAT];
__device__ __align__(16) float d_w[(size_t)GG * NN * MM];
__device__ float4 d_roip[NN];
__device__ float4 d_refp[MM];
__device__ __align__(16) float  d_po[(size_t)NSPLIT * NN * FEAT];
__device__ float2 d_pstat[NSPLIT * GG * NN];
// tf32-rounded + k-permuted input copies (GEMM operands)
__device__ __align__(16) float d_ref32[MM * FEAT];
__device__ __align__(16) float d_roi32[NN * FEAT];
__device__ __align__(16) float d_Wq32[FEAT * FEAT];
__device__ __align__(16) float d_Wk32[FEAT * FEAT];
__device__ __align__(16) float d_Wv32[FEAT * FEAT];

// ---------------- helpers ----------------
__device__ __forceinline__ float tf32r(float x) {
    uint32_t u;
    asm("cvt.rna.tf32.f32 %0, %1;" : "=r"(u) : "f"(x));
    return __uint_as_float(u);
}
__device__ __forceinline__ void mma8(float* c, const uint32_t* a, const uint32_t* b) {
    asm volatile(
        "mma.sync.aligned.m16n8k8.row.col.f32.tf32.tf32.f32 "
        "{%0,%1,%2,%3}, {%4,%5,%6,%7}, {%8,%9}, {%0,%1,%2,%3};"
        : "+f"(c[0]), "+f"(c[1]), "+f"(c[2]), "+f"(c[3])
        : "r"(a[0]), "r"(a[1]), "r"(a[2]), "r"(a[3]), "r"(b[0]), "r"(b[1]));
}
__device__ __forceinline__ unsigned long long fma2(unsigned long long a,
                                                   unsigned long long b,
                                                   unsigned long long c) {
    unsigned long long d;
    asm("fma.rn.f32x2 %0, %1, %2, %3;" : "=l"(d) : "l"(a), "l"(b), "l"(c));
    return d;
}
__device__ __forceinline__ unsigned long long pk(float a, float b) {
    unsigned long long v;
    asm("mov.b64 %0, {%1,%2};" : "=l"(v) : "f"(a), "f"(b));
    return v;
}
__device__ __forceinline__ float2 unpk(unsigned long long v) {
    float2 r;
    asm("mov.b64 {%0,%1}, %2;" : "=f"(r.x), "=f"(r.y) : "l"(v));
    return r;
}
__device__ __forceinline__ void fast_sincos(float x, float* s, float* c) {
    float n = rintf(x * 0.15915494309189535f);
    float r = fmaf(n, -6.28125f, x);
    r = fmaf(n, -1.9353071795864769e-3f, r);
    *s = __sinf(r);
    *c = __cosf(r);
}
__device__ __forceinline__ void cpa16(void* s, const void* g) {
    uint32_t sa = (uint32_t)__cvta_generic_to_shared(s);
    asm volatile("cp.async.ca.shared.global [%0], [%1], 16;" :: "r"(sa), "l"(g));
}
#define CP_COMMIT() asm volatile("cp.async.commit_group;" ::: "memory")
#define CP_WAIT(n)  asm volatile("cp.async.wait_group %0;" :: "n"(n) : "memory")

// ---------------- box param prep ----------------
__global__ void prep_boxes_kernel(const float* __restrict__ bbox,
                                  const float* __restrict__ refb)
{
    int i = blockIdx.x * 256 + threadIdx.x;
    if (i < NN) {
        float x0 = bbox[i*4+0], y0 = bbox[i*4+1], x1 = bbox[i*4+2], y1 = bbox[i*4+3];
        d_roip[i] = make_float4(0.5f*(x0+x1), 0.5f*(y0+y1), x1 - x0 + 1.0f, y1 - y0 + 1.0f);
    }
    if (i < MM) {
        float x0 = refb[i*4+0], y0 = refb[i*4+1], x1 = refb[i*4+2], y1 = refb[i*4+3];
        d_refp[i] = make_float4(0.5f*(x0+x1), 0.5f*(y0+y1), x1 - x0 + 1.0f, y1 - y0 + 1.0f);
    }
}

// ---------------- tf32 round + k-permute inputs ----------------
__global__ __launch_bounds__(256)
void prep_tf32(const float* __restrict__ roi, const float* __restrict__ ref,
               const float* __restrict__ Wq, const float* __restrict__ Wk,
               const float* __restrict__ Wv)
{
    size_t i8 = ((size_t)blockIdx.x * 256 + threadIdx.x) * 8;
    const float* src; float* dst;
    const size_t SREF = (size_t)MM * FEAT;
    const size_t SROI = (size_t)NN * FEAT;
    const size_t SW   = (size_t)FEAT * FEAT;
    if (i8 < SREF)                         { src = ref + i8;                 dst = d_ref32 + i8; }
    else if (i8 < SREF + SROI)             { src = roi + (i8 - SREF);        dst = d_roi32 + (i8 - SREF); }
    else if (i8 < SREF + SROI + SW)        { src = Wq + (i8 - SREF - SROI);  dst = d_Wq32 + (i8 - SREF - SROI); }
    else if (i8 < SREF + SROI + 2*SW)      { src = Wk + (i8 - SREF - SROI - SW);   dst = d_Wk32 + (i8 - SREF - SROI - SW); }
    else                                   { src = Wv + (i8 - SREF - SROI - 2*SW); dst = d_Wv32 + (i8 - SREF - SROI - 2*SW); }
    float4 in0 = *(const float4*)(src);
    float4 in1 = *(const float4*)(src + 4);
    float4 o0 = make_float4(tf32r(in0.x), tf32r(in1.x), tf32r(in0.y), tf32r(in1.y));
    float4 o1 = make_float4(tf32r(in0.z), tf32r(in1.z), tf32r(in0.w), tf32r(in1.w));
    *(float4*)(dst)     = o0;
    *(float4*)(dst + 4) = o1;
}

// ---------------- position prior:  w[g][n][m] = relu(Wg.pe)+1e-6 ----------------
__global__ __launch_bounds__(128)
void w_kernel(const float* __restrict__ Wg_w, const float* __restrict__ Wg_b)
{
    __shared__ __align__(16) float wg[GG * 64];
    __shared__ float wgb[GG];
    int n = blockIdx.y;
    int m = blockIdx.x * 128 + threadIdx.x;
    for (int t = threadIdx.x; t < GG * 64; t += 128) wg[t] = Wg_w[t];
    if (threadIdx.x < GG) wgb[threadIdx.x] = Wg_b[threadIdx.x];
    float4 rp = d_roip[n];
    float4 fp = d_refp[m];
    __syncthreads();

    float pos[4];
    pos[0] = logf(fabsf((rp.x - fp.x) / rp.z) + 1e-3f);
    pos[1] = logf(fabsf((rp.y - fp.y) / rp.w) + 1e-3f);
    pos[2] = logf(rp.z / fp.z);
    pos[3] = logf(rp.w / fp.w);

    const float rdm[8] = {1.0f, 0.42169650f, 0.17782794f, 0.074989421f,
                          0.031622777f, 0.013335214f, 0.0056234133f, 0.0023713737f};
    unsigned long long e2[32];
#pragma unroll
    for (int i = 0; i < 4; i++) {
        float p100 = pos[i] * 100.0f;
#pragma unroll
        for (int f = 0; f < 8; f += 2) {
            float s0, c0, s1, c1;
            fast_sincos(p100 * rdm[f],     &s0, &c0);
            fast_sincos(p100 * rdm[f + 1], &s1, &c1);
            e2[i*8 +     (f >> 1)] = pk(s0, s1);
            e2[i*8 + 4 + (f >> 1)] = pk(c0, c1);
        }
    }

    const unsigned long long* wg64 = (const unsigned long long*)wg;
    size_t base = (size_t)n * MM + m;
#pragma unroll 1
    for (int g = 0; g < GG; g++) {
        unsigned long long a0 = 0ull, a1 = 0ull;
#pragma unroll
        for (int j = 0; j < 32; j += 2) {
            a0 = fma2(wg64[g*32 + j],     e2[j],     a0);
            a1 = fma2(wg64[g*32 + j + 1], e2[j + 1], a1);
        }
        float2 f0 = unpk(a0), f1 = unpk(a1);
        float a = wgb[g] + ((f0.x + f0.y) + (f1.x + f1.y));
        d_w[(size_t)g * NN * MM + base] = fmaxf(a, 0.0f) + 1e-6f;
    }
}

// ---------------- mega GEMM: 128x128 tile, 2 CTA/SM, 4-stage, ONE barrier/iter ----
// 288 CTAs: 0..127 -> k, 128..255 -> v, 256..287 -> q.
#define GSTAGES 4
#define STG_F 4096

__device__ __forceinline__ void gg_stage(float* Sb, const float* Ap, const float* Bp,
                                         int k0, int tid)
{
#pragma unroll
    for (int i = 0; i < 2; i++) {
        int item = tid + i * 256;           // 0..511
        int r = item >> 2, q = item & 3;
        int g = q >> 1, h = q & 1;
        cpa16(Sb + g*1024 + r*8 + h*4, Ap + (size_t)r * FEAT + k0 + g*8 + h*4);
    }
#pragma unroll
    for (int i = 0; i < 2; i++) {
        int item = tid + i * 256;
        int r = item >> 2, q = item & 3;
        int g = q >> 1, h = q & 1;
        cpa16(Sb + 2048 + g*1024 + r*8 + h*4, Bp + (size_t)r * FEAT + k0 + g*8 + h*4);
    }
}

__global__ __launch_bounds__(256, 2)
void megagemm(const float* __restrict__ Wq_b, const float* __restrict__ Wk_b,
              const float* __restrict__ u)
{
    extern __shared__ __align__(16) float smg[];   // [GSTAGES][STG_F]

    int id = blockIdx.x;
    const float *A, *B, *bias = nullptr, *bias2 = nullptr;
    float scale = 1.0f; float* C; int br, bo; bool isV = false;
    if (id < 128) {
        A = d_ref32; br = (id >> 3) * 128; bo = (id & 7) * 128;
        B = d_Wk32 + (size_t)bo * FEAT; bias = Wk_b + bo; C = d_k;
    } else if (id < 256) {
        int i2 = id - 128;
        A = d_ref32; br = (i2 >> 3) * 128; bo = (i2 & 7) * 128;
        B = d_Wv32 + (size_t)bo * FEAT; C = d_v; isV = true;
    } else {
        int i2 = id - 256;
        A = d_roi32; br = (i2 >> 3) * 128; bo = (i2 & 7) * 128;
        B = d_Wq32 + (size_t)bo * FEAT; bias = Wq_b + bo; bias2 = u + bo;
        C = d_q; scale = 0.125f;
    }

    int tid = threadIdx.x, wid = tid >> 5, lane = tid & 31;
    int gr = lane >> 2, t = lane & 3;
    int wm = (wid >> 2) * 64;          // 0,64
    int wn = (wid & 3) * 32;           // 0,32,64,96

    const float* Ap = A + (size_t)br * FEAT;

    float acc[4][4][4];
#pragma unroll
    for (int i = 0; i < 4; i++)
#pragma unroll
        for (int j = 0; j < 4; j++)
#pragma unroll
            for (int q = 0; q < 4; q++) acc[i][j][q] = 0.0f;

    // preload GSTAGES-1 stages
#pragma unroll
    for (int s = 0; s < GSTAGES - 1; s++) {
        gg_stage(smg + s * STG_F, Ap, B, s * 16, tid);
        CP_COMMIT();
    }

    for (int it = 0; it < FEAT / 16; it++) {
        CP_WAIT(GSTAGES - 2);      // stage `it` landed (for this thread)
        __syncthreads();           // ...and visible to all threads; also: every
                                   // warp finished computing stage it-1
        // refill buffer (it+GSTAGES-1)&3 == (it-1)&3 — consumed at it-1, safe.
        if (it + GSTAGES - 1 < FEAT / 16)
            gg_stage(smg + ((it + GSTAGES - 1) & (GSTAGES - 1)) * STG_F,
                     Ap, B, (it + GSTAGES - 1) * 16, tid);
        CP_COMMIT();

        const float* Sb = smg + (it & (GSTAGES - 1)) * STG_F;
#pragma unroll
        for (int g = 0; g < 2; g++) {
            const float* Ac = Sb + g * 1024;
            const float* Bc = Sb + 2048 + g * 1024;
            uint32_t a[4][4], b[4][2];
#pragma unroll
            for (int mt = 0; mt < 4; mt++) {
                float2 lo = *(const float2*)&Ac[(wm + mt*16 + gr    ) * 8 + 2*t];
                float2 hi = *(const float2*)&Ac[(wm + mt*16 + gr + 8) * 8 + 2*t];
                a[mt][0] = __float_as_uint(lo.x);
                a[mt][1] = __float_as_uint(hi.x);
                a[mt][2] = __float_as_uint(lo.y);
                a[mt][3] = __float_as_uint(hi.y);
            }
#pragma unroll
            for (int nt = 0; nt < 4; nt++) {
                float2 bb = *(const float2*)&Bc[(wn + nt*8 + gr) * 8 + 2*t];
                b[nt][0] = __float_as_uint(bb.x);
                b[nt][1] = __float_as_uint(bb.y);
            }
#pragma unroll
            for (int mt = 0; mt < 4; mt++)
#pragma unroll
                for (int nt = 0; nt < 4; nt++) mma8(acc[mt][nt], a[mt], b[nt]);
        }
    }

    // epilogue: k/q permuted column writes; V plain
#pragma unroll
    for (int mt = 0; mt < 4; mt++) {
        int r0 = br + wm + mt*16 + gr;
#pragma unroll
        for (int nt = 0; nt < 4; nt++) {
            int lo = wn + nt*8 + 2*t;
            float v0 = acc[mt][nt][0], v1 = acc[mt][nt][1];
            float v2 = acc[mt][nt][2], v3 = acc[mt][nt][3];
            if (bias)  { float b0 = bias[lo],  b1 = bias[lo+1];  v0 += b0; v2 += b0; v1 += b1; v3 += b1; }
            if (bias2) { float b0 = bias2[lo], b1 = bias2[lo+1]; v0 += b0; v2 += b0; v1 += b1; v3 += b1; }
            v0 = tf32r(v0 * scale); v1 = tf32r(v1 * scale);
            v2 = tf32r(v2 * scale); v3 = tf32r(v3 * scale);
            if (isV) {
                *(float2*)&C[(size_t)r0 * FEAT + bo + lo]       = make_float2(v0, v1);
                *(float2*)&C[(size_t)(r0 + 8) * FEAT + bo + lo] = make_float2(v2, v3);
            } else {
                int c0 = lo & 7;
                int base = bo + (lo & ~7);
                int col0 = base + ((c0 & 3) << 1) + (c0 >> 2);
                int c1 = c0 + 1;
                int col1 = base + ((c1 & 3) << 1) + (c1 >> 2);
                C[(size_t)r0 * FEAT + col0]       = v0;
                C[(size_t)r0 * FEAT + col1]       = v1;
                C[(size_t)(r0 + 8) * FEAT + col0] = v2;
                C[(size_t)(r0 + 8) * FEAT + col1] = v3;
            }
        }
    }
}

// ---------------- split-KV flash attention (partials), ONE barrier/tile ----------
#define ST 72   // stride (floats): K LDS.64 frags conflict-free; V LDS.32 frags conflict-free
#define BUFSZ (2 * 64 * ST)
__device__ __forceinline__ void attn_stage(float* Kb, float* Vb, int m0, int g, int tid)
{
    for (int idx = tid; idx < 1024; idx += 128) {
        int r = idx >> 4, c4 = (idx & 15) * 4;
        cpa16(&Kb[r*ST + c4], &d_k[(size_t)(m0 + r) * FEAT + g*64 + c4]);
        cpa16(&Vb[r*ST + c4], &d_v[(size_t)(m0 + r) * FEAT + g*64 + c4]);
    }
}

__global__ __launch_bounds__(128, 3)
void attn_split_kernel()
{
    extern __shared__ __align__(16) float sm[];

    int g = blockIdx.y, n0 = blockIdx.x * 64, sp = blockIdx.z;
    int mbase = sp * (MM / NSPLIT);
    int tid = threadIdx.x, wid = tid >> 5, lane = tid & 31;
    int gr = lane >> 2, t = lane & 3;
    int row0 = wid * 16 + gr, row1 = row0 + 8;

    // Q fragments via LDG.64 (d_q k-permuted: pos 2t holds k=t, pos 2t+1 holds k=t+4)
    uint32_t qf[8][4];
#pragma unroll
    for (int ks8 = 0; ks8 < 8; ks8++) {
        const float* qb = d_q + (size_t)n0 * FEAT + g * 64 + ks8 * 8 + 2*t;
        float2 q0 = *(const float2*)(qb + (size_t)row0 * FEAT);
        float2 q1 = *(const float2*)(qb + (size_t)row1 * FEAT);
        qf[ks8][0] = __float_as_uint(q0.x);
        qf[ks8][1] = __float_as_uint(q1.x);
        qf[ks8][2] = __float_as_uint(q0.y);
        qf[ks8][3] = __float_as_uint(q1.y);
    }

    float accO[8][4];
#pragma unroll
    for (int i = 0; i < 8; i++)
#pragma unroll
        for (int j = 0; j < 4; j++) accO[i][j] = 0.0f;
    float rmax0 = -1e30f, rmax1 = -1e30f, rsum0 = 0.0f, rsum1 = 0.0f;

    const float* wbase = d_w + ((size_t)g * NN + n0) * MM + mbase;
    const int NT = (MM / NSPLIT) / 64;

    attn_stage(sm, sm + 64 * ST, mbase, g, tid);
    CP_COMMIT();

    for (int it = 0; it < NT; it++) {
        CP_WAIT(0);
        __syncthreads();           // tile `it` visible; all warps done with it-1
        float* Kb = sm + (it & 1) * BUFSZ;
        float* Vb = Kb + 64 * ST;
        if (it + 1 < NT) {
            float* Kn = sm + ((it + 1) & 1) * BUFSZ;
            attn_stage(Kn, Kn + 64 * ST, mbase + (it + 1) * 64, g, tid);
            CP_COMMIT();
        }

        // hoist prior-weight loads: LDG latency covered by the S-MMA train below
        const float* wt = wbase + it * 64;
        float2 w0[8], w1[8];
#pragma unroll
        for (int nt = 0; nt < 8; nt++) {
            w0[nt] = *(const float2*)&wt[(size_t)row0 * MM + nt*8 + 2*t];
            w1[nt] = *(const float2*)&wt[(size_t)row1 * MM + nt*8 + 2*t];
        }

        // S = Q K^T  (K frags via LDS.64 on permuted layout)
        float s[8][4];
#pragma unroll
        for (int i = 0; i < 8; i++)
#pragma unroll
            for (int j = 0; j < 4; j++) s[i][j] = 0.0f;
#pragma unroll
        for (int ks = 0; ks < 8; ks++) {
#pragma unroll
            for (int nt = 0; nt < 8; nt++) {
                float2 kk = *(const float2*)&Kb[(nt*8 + gr)*ST + ks*8 + 2*t];
                uint32_t b[2];
                b[0] = __float_as_uint(kk.x);
                b[1] = __float_as_uint(kk.y);
                mma8(s[nt], qf[ks], b);
            }
        }

        float m0v = rmax0, m1v = rmax1;
#pragma unroll
        for (int nt = 0; nt < 8; nt++) {
            m0v = fmaxf(m0v, fmaxf(s[nt][0], s[nt][1]));
            m1v = fmaxf(m1v, fmaxf(s[nt][2], s[nt][3]));
        }
        m0v = fmaxf(m0v, __shfl_xor_sync(0xffffffffu, m0v, 1));
        m0v = fmaxf(m0v, __shfl_xor_sync(0xffffffffu, m0v, 2));
        m1v = fmaxf(m1v, __shfl_xor_sync(0xffffffffu, m1v, 1));
        m1v = fmaxf(m1v, __shfl_xor_sync(0xffffffffu, m1v, 2));
        float fac0 = __expf(rmax0 - m0v), fac1 = __expf(rmax1 - m1v);
        rmax0 = m0v; rmax1 = m1v;
        float sum0 = 0.0f, sum1 = 0.0f;
#pragma unroll
        for (int nt = 0; nt < 8; nt++) {
            float p0 = w0[nt].x * __expf(s[nt][0] - m0v);
            float p1 = w0[nt].y * __expf(s[nt][1] - m0v);
            float p2 = w1[nt].x * __expf(s[nt][2] - m1v);
            float p3 = w1[nt].y * __expf(s[nt][3] - m1v);
            sum0 += p0 + p1; sum1 += p2 + p3;
            // fed raw to HMMA: tf32 truncation in HW (cutlass-style), no CVT cost
            s[nt][0] = p0; s[nt][1] = p1;
            s[nt][2] = p2; s[nt][3] = p3;
        }
        sum0 += __shfl_xor_sync(0xffffffffu, sum0, 1);
        sum0 += __shfl_xor_sync(0xffffffffu, sum0, 2);
        sum1 += __shfl_xor_sync(0xffffffffu, sum1, 1);
        sum1 += __shfl_xor_sync(0xffffffffu, sum1, 2);
        rsum0 = rsum0 * fac0 + sum0;
        rsum1 = rsum1 * fac1 + sum1;
#pragma unroll
        for (int dt = 0; dt < 8; dt++) {
            accO[dt][0] *= fac0; accO[dt][1] *= fac0;
            accO[dt][2] *= fac1; accO[dt][3] *= fac1;
        }

        // O += P V : P transposed via shuffles; V frags via conflict-free LDS.32
        int sA = (lane & ~3) | (t >> 1);
        int sB = sA + 2;
        bool odd = (t & 1);
#pragma unroll
        for (int ks = 0; ks < 8; ks++) {
            float p0 = s[ks][0], p1 = s[ks][1], p2 = s[ks][2], p3 = s[ks][3];
            float e0 = __shfl_sync(0xffffffffu, p0, sA);
            float e1 = __shfl_sync(0xffffffffu, p1, sA);
            float e2 = __shfl_sync(0xffffffffu, p2, sA);
            float e3 = __shfl_sync(0xffffffffu, p3, sA);
            float f0 = __shfl_sync(0xffffffffu, p0, sB);
            float f1 = __shfl_sync(0xffffffffu, p1, sB);
            float f2 = __shfl_sync(0xffffffffu, p2, sB);
            float f3 = __shfl_sync(0xffffffffu, p3, sB);
            uint32_t a[4];
            a[0] = __float_as_uint(odd ? e1 : e0);
            a[1] = __float_as_uint(odd ? e3 : e2);
            a[2] = __float_as_uint(odd ? f1 : f0);
            a[3] = __float_as_uint(odd ? f3 : f2);
#pragma unroll
            for (int dt = 0; dt < 8; dt++) {
                uint32_t b[2];
                b[0] = __float_as_uint(Vb[(ks*8 + t    )*ST + dt*8 + gr]);
                b[1] = __float_as_uint(Vb[(ks*8 + t + 4)*ST + dt*8 + gr]);
                mma8(accO[dt], a, b);
            }
        }
    }

    if (t == 0) {
        d_pstat[((size_t)sp * GG + g) * NN + n0 + row0] = make_float2(rmax0, rsum0);
        d_pstat[((size_t)sp * GG + g) * NN + n0 + row1] = make_float2(rmax1, rsum1);
    }
    float* po = d_po + (size_t)sp * NN * FEAT;
#pragma unroll
    for (int dt = 0; dt < 8; dt++) {
        int o = g*64 + dt*8 + 2*t;
        *(float2*)&po[(size_t)(n0 + row0) * FEAT + o] = make_float2(accO[dt][0], accO[dt][1]);
        *(float2*)&po[(size_t)(n0 + row1) * FEAT + o] = make_float2(accO[dt][2], accO[dt][3]);
    }
}

// ---------------- merge partials -> final output ----------------
__global__ __launch_bounds__(256)
void merge_kernel(const float* __restrict__ Wv_b, float* __restrict__ out)
{
    int idx = blockIdx.x * 256 + threadIdx.x;
    int n = idx >> 10, o = idx & 1023, g = o >> 6;
    float2 st[NSPLIT];
    float M = -1e30f;
#pragma unroll
    for (int s = 0; s < NSPLIT; s++) {
        st[s] = d_pstat[((size_t)s * GG + g) * NN + n];
        M = fmaxf(M, st[s].x);
    }
    float num = 0.0f, den = 0.0f;
#pragma unroll
    for (int s = 0; s < NSPLIT; s++) {
        float w = __expf(st[s].x - M);
        num += d_po[((size_t)s * NN + n) * FEAT + o] * w;
        den += st[s].y * w;
    }
    out[idx] = num / den + Wv_b[o];
}

// ---------------- launch ----------------
extern "C" void kernel_launch(void* const* d_in, const int* in_sizes, int n_in,
                              void* d_out, int out_size)
{
    const float* bbox     = (const float*)d_in[0];
    const float* ref_bbox = (const float*)d_in[1];
    const float* roi_feat = (const float*)d_in[2];
    const float* ref_feat = (const float*)d_in[3];
    const float* Wg_w     = (const float*)d_in[4];
    const float* Wg_b     = (const float*)d_in[5];
    const float* Wq_w     = (const float*)d_in[6];
    const float* Wq_b     = (const float*)d_in[7];
    const float* Wk_w     = (const float*)d_in[8];
    const float* Wk_b     = (const float*)d_in[9];
    const float* Wv_w     = (const float*)d_in[10];
    const float* Wv_b     = (const float*)d_in[11];
    const float* u        = (const float*)d_in[12];
    float* out = (float*)d_out;

    (void)in_sizes; (void)n_in; (void)out_size;

    static const int ATTN_SMEM = 2 * BUFSZ * 4;            // 73728 B
    static const int GEMM_SMEM = GSTAGES * STG_F * 4;      // 65536 B
    cudaFuncSetAttribute(attn_split_kernel, cudaFuncAttributeMaxDynamicSharedMemorySize, ATTN_SMEM);
    cudaFuncSetAttribute(megagemm, cudaFuncAttributeMaxDynamicSharedMemorySize, GEMM_SMEM);

    // Fork/join: w_kernel overlaps the GEMM chain on a side stream.
    cudaStream_t s1;
    cudaEvent_t evFork, evJoin;
    cudaStreamCreateWithFlags(&s1, cudaStreamNonBlocking);
    cudaEventCreateWithFlags(&evFork, cudaEventDisableTiming);
    cudaEventCreateWithFlags(&evJoin, cudaEventDisableTiming);

    prep_boxes_kernel<<<8, 256>>>(bbox, ref_bbox);
    cudaEventRecord(evFork, 0);
    cudaStreamWaitEvent(s1, evFork, 0);

    w_kernel<<<dim3(MM / 128, NN), 128, 0, s1>>>(Wg_w, Wg_b);
    cudaEventRecord(evJoin, s1);

    prep_tf32<<<2816, 256>>>(roi_feat, ref_feat, Wq_w, Wk_w, Wv_w);
    megagemm<<<288, 256, GEMM_SMEM>>>(Wq_b, Wk_b, u);

    cudaStreamWaitEvent(0, evJoin, 0);
    attn_split_kernel<<<dim3(NN / 64, GG, NSPLIT), 128, ATTN_SMEM>>>();
    merge_kernel<<<NN * FEAT / 256, 256>>>(Wv_b, out);
}

// round 14
// speedup vs baseline: 1.5126x; 1.5126x over previous
#include <cuda_runtime.h>
#include <math.h>
#include <stdint.h>

#define NN 512
#define MM 2048
#define FEAT 1024
#define GG 16
#define DG 64
#define NSPLIT 4

// ---------------- scratch (device globals; no allocation) ----------------
// d_q/d_k are k-permuted: within each 8-float k-group, stored pos p(k)=(k&3)*2+(k>>2),
// i.e. storage order {0,4,1,5,2,6,3,7}. d_v is PLAIN layout.
__device__ __align__(16) float d_q[NN * FEAT];
__device__ __align__(16) float d_k[MM * FEAT];
__device__ __align__(16) float d_v[MM * FEAT];
__device__ __align__(16) float d_w[(size_t)GG * NN * MM];
__device__ float4 d_roip[NN];
__device__ float4 d_refp[MM];
__device__ __align__(16) float  d_po[(size_t)NSPLIT * NN * FEAT];
__device__ float2 d_pstat[NSPLIT * GG * NN];
// tf32-rounded + k-permuted input copies (GEMM operands)
__device__ __align__(16) float d_ref32[MM * FEAT];
__device__ __align__(16) float d_roi32[NN * FEAT];
__device__ __align__(16) float d_Wq32[FEAT * FEAT];
__device__ __align__(16) float d_Wk32[FEAT * FEAT];
__device__ __align__(16) float d_Wv32[FEAT * FEAT];

// ---------------- helpers ----------------
__device__ __forceinline__ float tf32r(float x) {
    uint32_t u;
    asm("cvt.rna.tf32.f32 %0, %1;" : "=r"(u) : "f"(x));
    return __uint_as_float(u);
}
__device__ __forceinline__ void mma8(float* c, const uint32_t* a, const uint32_t* b) {
    asm volatile(
        "mma.sync.aligned.m16n8k8.row.col.f32.tf32.tf32.f32 "
        "{%0,%1,%2,%3}, {%4,%5,%6,%7}, {%8,%9}, {%0,%1,%2,%3};"
        : "+f"(c[0]), "+f"(c[1]), "+f"(c[2]), "+f"(c[3])
        : "r"(a[0]), "r"(a[1]), "r"(a[2]), "r"(a[3]), "r"(b[0]), "r"(b[1]));
}
__device__ __forceinline__ unsigned long long fma2(unsigned long long a,
                                                   unsigned long long b,
                                                   unsigned long long c) {
    unsigned long long d;
    asm("fma.rn.f32x2 %0, %1, %2, %3;" : "=l"(d) : "l"(a), "l"(b), "l"(c));
    return d;
}
__device__ __forceinline__ unsigned long long pk(float a, float b) {
    unsigned long long v;
    asm("mov.b64 %0, {%1,%2};" : "=l"(v) : "f"(a), "f"(b));
    return v;
}
__device__ __forceinline__ float2 unpk(unsigned long long v) {
    float2 r;
    asm("mov.b64 {%0,%1}, %2;" : "=f"(r.x), "=f"(r.y) : "l"(v));
    return r;
}
__device__ __forceinline__ void fast_sincos(float x, float* s, float* c) {
    float n = rintf(x * 0.15915494309189535f);
    float r = fmaf(n, -6.28125f, x);
    r = fmaf(n, -1.9353071795864769e-3f, r);
    *s = __sinf(r);
    *c = __cosf(r);
}
__device__ __forceinline__ void cpa16(void* s, const void* g) {
    uint32_t sa = (uint32_t)__cvta_generic_to_shared(s);
    asm volatile("cp.async.ca.shared.global [%0], [%1], 16;" :: "r"(sa), "l"(g));
}
#define CP_COMMIT() asm volatile("cp.async.commit_group;" ::: "memory")
#define CP_WAIT(n)  asm volatile("cp.async.wait_group %0;" :: "n"(n) : "memory")

// ---------------- box param prep ----------------
__global__ void prep_boxes_kernel(const float* __restrict__ bbox,
                                  const float* __restrict__ refb)
{
    int i = blockIdx.x * 256 + threadIdx.x;
    if (i < NN) {
        float x0 = bbox[i*4+0], y0 = bbox[i*4+1], x1 = bbox[i*4+2], y1 = bbox[i*4+3];
        d_roip[i] = make_float4(0.5f*(x0+x1), 0.5f*(y0+y1), x1 - x0 + 1.0f, y1 - y0 + 1.0f);
    }
    if (i < MM) {
        float x0 = refb[i*4+0], y0 = refb[i*4+1], x1 = refb[i*4+2], y1 = refb[i*4+3];
        d_refp[i] = make_float4(0.5f*(x0+x1), 0.5f*(y0+y1), x1 - x0 + 1.0f, y1 - y0 + 1.0f);
    }
}

// ---------------- tf32 round + k-permute inputs ----------------
__global__ __launch_bounds__(256)
void prep_tf32(const float* __restrict__ roi, const float* __restrict__ ref,
               const float* __restrict__ Wq, const float* __restrict__ Wk,
               const float* __restrict__ Wv)
{
    size_t i8 = ((size_t)blockIdx.x * 256 + threadIdx.x) * 8;
    const float* src; float* dst;
    const size_t SREF = (size_t)MM * FEAT;
    const size_t SROI = (size_t)NN * FEAT;
    const size_t SW   = (size_t)FEAT * FEAT;
    if (i8 < SREF)                         { src = ref + i8;                 dst = d_ref32 + i8; }
    else if (i8 < SREF + SROI)             { src = roi + (i8 - SREF);        dst = d_roi32 + (i8 - SREF); }
    else if (i8 < SREF + SROI + SW)        { src = Wq + (i8 - SREF - SROI);  dst = d_Wq32 + (i8 - SREF - SROI); }
    else if (i8 < SREF + SROI + 2*SW)      { src = Wk + (i8 - SREF - SROI - SW);   dst = d_Wk32 + (i8 - SREF - SROI - SW); }
    else                                   { src = Wv + (i8 - SREF - SROI - 2*SW); dst = d_Wv32 + (i8 - SREF - SROI - 2*SW); }
    float4 in0 = *(const float4*)(src);
    float4 in1 = *(const float4*)(src + 4);
    float4 o0 = make_float4(tf32r(in0.x), tf32r(in1.x), tf32r(in0.y), tf32r(in1.y));
    float4 o1 = make_float4(tf32r(in0.z), tf32r(in1.z), tf32r(in0.w), tf32r(in1.w));
    *(float4*)(dst)     = o0;
    *(float4*)(dst + 4) = o1;
}

// ---------------- position prior:  w[g][n][m] = relu(Wg.pe)+1e-6 ----------------
__global__ __launch_bounds__(128)
void w_kernel(const float* __restrict__ Wg_w, const float* __restrict__ Wg_b)
{
    __shared__ __align__(16) float wg[GG * 64];
    __shared__ float wgb[GG];
    int n = blockIdx.y;
    int m = blockIdx.x * 128 + threadIdx.x;
    for (int t = threadIdx.x; t < GG * 64; t += 128) wg[t] = Wg_w[t];
    if (threadIdx.x < GG) wgb[threadIdx.x] = Wg_b[threadIdx.x];
    float4 rp = d_roip[n];
    float4 fp = d_refp[m];
    __syncthreads();

    float pos[4];
    pos[0] = logf(fabsf((rp.x - fp.x) / rp.z) + 1e-3f);
    pos[1] = logf(fabsf((rp.y - fp.y) / rp.w) + 1e-3f);
    pos[2] = logf(rp.z / fp.z);
    pos[3] = logf(rp.w / fp.w);

    const float rdm[8] = {1.0f, 0.42169650f, 0.17782794f, 0.074989421f,
                          0.031622777f, 0.013335214f, 0.0056234133f, 0.0023713737f};
    unsigned long long e2[32];
#pragma unroll
    for (int i = 0; i < 4; i++) {
        float p100 = pos[i] * 100.0f;
#pragma unroll
        for (int f = 0; f < 8; f += 2) {
            float s0, c0, s1, c1;
            fast_sincos(p100 * rdm[f],     &s0, &c0);
            fast_sincos(p100 * rdm[f + 1], &s1, &c1);
            e2[i*8 +     (f >> 1)] = pk(s0, s1);
            e2[i*8 + 4 + (f >> 1)] = pk(c0, c1);
        }
    }

    const unsigned long long* wg64 = (const unsigned long long*)wg;
    size_t base = (size_t)n * MM + m;
#pragma unroll 1
    for (int g = 0; g < GG; g++) {
        unsigned long long a0 = 0ull, a1 = 0ull;
#pragma unroll
        for (int j = 0; j < 32; j += 2) {
            a0 = fma2(wg64[g*32 + j],     e2[j],     a0);
            a1 = fma2(wg64[g*32 + j + 1], e2[j + 1], a1);
        }
        float2 f0 = unpk(a0), f1 = unpk(a1);
        float a = wgb[g] + ((f0.x + f0.y) + (f1.x + f1.y));
        d_w[(size_t)g * NN * MM + base] = fmaxf(a, 0.0f) + 1e-6f;
    }
}

// ---------------- mega GEMM: 128x128 tile, 2 CTA/SM, 4-stage cp.async (R12) ------
// 288 CTAs: 0..127 -> k, 128..255 -> v, 256..287 -> q.
#define GSTAGES 4
#define STG_F 4096

__device__ __forceinline__ void gg_stage(float* Sb, const float* Ap, const float* Bp,
                                         int k0, int tid)
{
#pragma unroll
    for (int i = 0; i < 2; i++) {
        int item = tid + i * 256;           // 0..511
        int r = item >> 2, q = item & 3;
        int g = q >> 1, h = q & 1;
        cpa16(Sb + g*1024 + r*8 + h*4, Ap + (size_t)r * FEAT + k0 + g*8 + h*4);
    }
#pragma unroll
    for (int i = 0; i < 2; i++) {
        int item = tid + i * 256;
        int r = item >> 2, q = item & 3;
        int g = q >> 1, h = q & 1;
        cpa16(Sb + 2048 + g*1024 + r*8 + h*4, Bp + (size_t)r * FEAT + k0 + g*8 + h*4);
    }
}

__global__ __launch_bounds__(256, 2)
void megagemm(const float* __restrict__ Wq_b, const float* __restrict__ Wk_b,
              const float* __restrict__ u)
{
    extern __shared__ __align__(16) float smg[];   // [GSTAGES][STG_F]

    int id = blockIdx.x;
    const float *A, *B, *bias = nullptr, *bias2 = nullptr;
    float scale = 1.0f; float* C; int br, bo; bool isV = false;
    if (id < 128) {
        A = d_ref32; br = (id >> 3) * 128; bo = (id & 7) * 128;
        B = d_Wk32 + (size_t)bo * FEAT; bias = Wk_b + bo; C = d_k;
    } else if (id < 256) {
        int i2 = id - 128;
        A = d_ref32; br = (i2 >> 3) * 128; bo = (i2 & 7) * 128;
        B = d_Wv32 + (size_t)bo * FEAT; C = d_v; isV = true;
    } else {
        int i2 = id - 256;
        A = d_roi32; br = (i2 >> 3) * 128; bo = (i2 & 7) * 128;
        B = d_Wq32 + (size_t)bo * FEAT; bias = Wq_b + bo; bias2 = u + bo;
        C = d_q; scale = 0.125f;
    }

    int tid = threadIdx.x, wid = tid >> 5, lane = tid & 31;
    int gr = lane >> 2, t = lane & 3;
    int wm = (wid >> 2) * 64;          // 0,64
    int wn = (wid & 3) * 32;           // 0,32,64,96

    const float* Ap = A + (size_t)br * FEAT;

    float acc[4][4][4];
#pragma unroll
    for (int i = 0; i < 4; i++)
#pragma unroll
        for (int j = 0; j < 4; j++)
#pragma unroll
            for (int q = 0; q < 4; q++) acc[i][j][q] = 0.0f;

#pragma unroll
    for (int s = 0; s < GSTAGES; s++) {
        gg_stage(smg + s * STG_F, Ap, B, s * 16, tid);
        CP_COMMIT();
    }

    for (int it = 0; it < FEAT / 16; it++) {
        CP_WAIT(GSTAGES - 1);
        __syncthreads();
        const float* Sb = smg + (it & (GSTAGES - 1)) * STG_F;
#pragma unroll
        for (int g = 0; g < 2; g++) {
            const float* Ac = Sb + g * 1024;
            const float* Bc = Sb + 2048 + g * 1024;
            uint32_t a[4][4], b[4][2];
#pragma unroll
            for (int mt = 0; mt < 4; mt++) {
                float2 lo = *(const float2*)&Ac[(wm + mt*16 + gr    ) * 8 + 2*t];
                float2 hi = *(const float2*)&Ac[(wm + mt*16 + gr + 8) * 8 + 2*t];
                a[mt][0] = __float_as_uint(lo.x);
                a[mt][1] = __float_as_uint(hi.x);
                a[mt][2] = __float_as_uint(lo.y);
                a[mt][3] = __float_as_uint(hi.y);
            }
#pragma unroll
            for (int nt = 0; nt < 4; nt++) {
                float2 bb = *(const float2*)&Bc[(wn + nt*8 + gr) * 8 + 2*t];
                b[nt][0] = __float_as_uint(bb.x);
                b[nt][1] = __float_as_uint(bb.y);
            }
#pragma unroll
            for (int mt = 0; mt < 4; mt++)
#pragma unroll
                for (int nt = 0; nt < 4; nt++) mma8(acc[mt][nt], a[mt], b[nt]);
        }
        __syncthreads();
        if (it + GSTAGES < FEAT / 16)
            gg_stage(smg + (it & (GSTAGES - 1)) * STG_F, Ap, B, (it + GSTAGES) * 16, tid);
        CP_COMMIT();
    }

    // epilogue: k/q permuted column writes; V plain
#pragma unroll
    for (int mt = 0; mt < 4; mt++) {
        int r0 = br + wm + mt*16 + gr;
#pragma unroll
        for (int nt = 0; nt < 4; nt++) {
            int lo = wn + nt*8 + 2*t;
            float v0 = acc[mt][nt][0], v1 = acc[mt][nt][1];
            float v2 = acc[mt][nt][2], v3 = acc[mt][nt][3];
            if (bias)  { float b0 = bias[lo],  b1 = bias[lo+1];  v0 += b0; v2 += b0; v1 += b1; v3 += b1; }
            if (bias2) { float b0 = bias2[lo], b1 = bias2[lo+1]; v0 += b0; v2 += b0; v1 += b1; v3 += b1; }
            v0 = tf32r(v0 * scale); v1 = tf32r(v1 * scale);
            v2 = tf32r(v2 * scale); v3 = tf32r(v3 * scale);
            if (isV) {
                *(float2*)&C[(size_t)r0 * FEAT + bo + lo]       = make_float2(v0, v1);
                *(float2*)&C[(size_t)(r0 + 8) * FEAT + bo + lo] = make_float2(v2, v3);
            } else {
                int c0 = lo & 7;
                int base = bo + (lo & ~7);
                int col0 = base + ((c0 & 3) << 1) + (c0 >> 2);
                int c1 = c0 + 1;
                int col1 = base + ((c1 & 3) << 1) + (c1 >> 2);
                C[(size_t)r0 * FEAT + col0]       = v0;
                C[(size_t)r0 * FEAT + col1]       = v1;
                C[(size_t)(r0 + 8) * FEAT + col0] = v2;
                C[(size_t)(r0 + 8) * FEAT + col1] = v3;
            }
        }
    }
}

// ---------------- split-KV flash attention (partials) — R12 structure ------------
#define ST 72   // stride (floats): K LDS.64 frags conflict-free; V LDS.32 frags conflict-free
#define BUFSZ (2 * 64 * ST)
__global__ __launch_bounds__(128, 3)
void attn_split_kernel()
{
    extern __shared__ __align__(16) float sm[];

    int g = blockIdx.y, n0 = blockIdx.x * 64, sp = blockIdx.z;
    int mbase = sp * (MM / NSPLIT);
    int tid = threadIdx.x, wid = tid >> 5, lane = tid & 31;
    int gr = lane >> 2, t = lane & 3;
    int row0 = wid * 16 + gr, row1 = row0 + 8;

    // Q fragments via LDG.64 (d_q k-permuted: pos 2t holds k=t, pos 2t+1 holds k=t+4)
    uint32_t qf[8][4];
#pragma unroll
    for (int ks8 = 0; ks8 < 8; ks8++) {
        const float* qb = d_q + (size_t)n0 * FEAT + g * 64 + ks8 * 8 + 2*t;
        float2 q0 = *(const float2*)(qb + (size_t)row0 * FEAT);
        float2 q1 = *(const float2*)(qb + (size_t)row1 * FEAT);
        qf[ks8][0] = __float_as_uint(q0.x);
        qf[ks8][1] = __float_as_uint(q1.x);
        qf[ks8][2] = __float_as_uint(q0.y);
        qf[ks8][3] = __float_as_uint(q1.y);
    }

    float accO[8][4];
#pragma unroll
    for (int i = 0; i < 8; i++)
#pragma unroll
        for (int j = 0; j < 4; j++) accO[i][j] = 0.0f;
    float rmax0 = -1e30f, rmax1 = -1e30f, rsum0 = 0.0f, rsum1 = 0.0f;

    const float* wbase = d_w + ((size_t)g * NN + n0) * MM + mbase;
    const int NT = (MM / NSPLIT) / 64;

    {
        float* Kb = sm; float* Vb = sm + 64 * ST;
        for (int idx = tid; idx < 1024; idx += 128) {
            int r = idx >> 4, c4 = (idx & 15) * 4;
            cpa16(&Kb[r*ST + c4], &d_k[(size_t)(mbase + r) * FEAT + g*64 + c4]);
            cpa16(&Vb[r*ST + c4], &d_v[(size_t)(mbase + r) * FEAT + g*64 + c4]);
        }
        CP_COMMIT();
    }

    for (int it = 0; it < NT; it++) {
        int buf = it & 1;
        float* Kb = sm + buf * BUFSZ;
        float* Vb = Kb + 64 * ST;
        if (it + 1 < NT) {
            float* Kn = sm + (buf ^ 1) * BUFSZ;
            float* Vn = Kn + 64 * ST;
            int m0 = mbase + (it + 1) * 64;
            for (int idx = tid; idx < 1024; idx += 128) {
                int r = idx >> 4, c4 = (idx & 15) * 4;
                cpa16(&Kn[r*ST + c4], &d_k[(size_t)(m0 + r) * FEAT + g*64 + c4]);
                cpa16(&Vn[r*ST + c4], &d_v[(size_t)(m0 + r) * FEAT + g*64 + c4]);
            }
            CP_COMMIT();
            CP_WAIT(1);
        } else {
            CP_WAIT(0);
        }
        __syncthreads();

        // hoisted prior-weight loads: LDG latency hidden under the S-MMA train
        const float* wt = wbase + it * 64;
        float2 w0[8], w1[8];
#pragma unroll
        for (int nt = 0; nt < 8; nt++) {
            w0[nt] = *(const float2*)&wt[(size_t)row0 * MM + nt*8 + 2*t];
            w1[nt] = *(const float2*)&wt[(size_t)row1 * MM + nt*8 + 2*t];
        }

        // S = Q K^T  (K frags via LDS.64 on permuted layout)
        float s[8][4];
#pragma unroll
        for (int i = 0; i < 8; i++)
#pragma unroll
            for (int j = 0; j < 4; j++) s[i][j] = 0.0f;
#pragma unroll
        for (int ks = 0; ks < 8; ks++) {
#pragma unroll
            for (int nt = 0; nt < 8; nt++) {
                float2 kk = *(const float2*)&Kb[(nt*8 + gr)*ST + ks*8 + 2*t];
                uint32_t b[2];
                b[0] = __float_as_uint(kk.x);
                b[1] = __float_as_uint(kk.y);
                mma8(s[nt], qf[ks], b);
            }
        }

        float m0v = rmax0, m1v = rmax1;
#pragma unroll
        for (int nt = 0; nt < 8; nt++) {
            m0v = fmaxf(m0v, fmaxf(s[nt][0], s[nt][1]));
            m1v = fmaxf(m1v, fmaxf(s[nt][2], s[nt][3]));
        }
        m0v = fmaxf(m0v, __shfl_xor_sync(0xffffffffu, m0v, 1));
        m0v = fmaxf(m0v, __shfl_xor_sync(0xffffffffu, m0v, 2));
        m1v = fmaxf(m1v, __shfl_xor_sync(0xffffffffu, m1v, 1));
        m1v = fmaxf(m1v, __shfl_xor_sync(0xffffffffu, m1v, 2));
        float fac0 = __expf(rmax0 - m0v), fac1 = __expf(rmax1 - m1v);
        rmax0 = m0v; rmax1 = m1v;
        float sum0 = 0.0f, sum1 = 0.0f;
#pragma unroll
        for (int nt = 0; nt < 8; nt++) {
            float p0 = w0[nt].x * __expf(s[nt][0] - m0v);
            float p1 = w0[nt].y * __expf(s[nt][1] - m0v);
            float p2 = w1[nt].x * __expf(s[nt][2] - m1v);
            float p3 = w1[nt].y * __expf(s[nt][3] - m1v);
            sum0 += p0 + p1; sum1 += p2 + p3;
            // fed raw to HMMA: tf32 truncation happens in HW, no CVT cost
            s[nt][0] = p0; s[nt][1] = p1;
            s[nt][2] = p2; s[nt][3] = p3;
        }
        sum0 += __shfl_xor_sync(0xffffffffu, sum0, 1);
        sum0 += __shfl_xor_sync(0xffffffffu, sum0, 2);
        sum1 += __shfl_xor_sync(0xffffffffu, sum1, 1);
        sum1 += __shfl_xor_sync(0xffffffffu, sum1, 2);
        rsum0 = rsum0 * fac0 + sum0;
        rsum1 = rsum1 * fac1 + sum1;
#pragma unroll
        for (int dt = 0; dt < 8; dt++) {
            accO[dt][0] *= fac0; accO[dt][1] *= fac0;
            accO[dt][2] *= fac1; accO[dt][3] *= fac1;
        }

        // O += P V : P transposed via shuffles; V frags via conflict-free LDS.32
        int sA = (lane & ~3) | (t >> 1);
        int sB = sA + 2;
        bool odd = (t & 1);
#pragma unroll
        for (int ks = 0; ks < 8; ks++) {
            float p0 = s[ks][0], p1 = s[ks][1], p2 = s[ks][2], p3 = s[ks][3];
            float e0 = __shfl_sync(0xffffffffu, p0, sA);
            float e1 = __shfl_sync(0xffffffffu, p1, sA);
            float e2 = __shfl_sync(0xffffffffu, p2, sA);
            float e3 = __shfl_sync(0xffffffffu, p3, sA);
            float f0 = __shfl_sync(0xffffffffu, p0, sB);
            float f1 = __shfl_sync(0xffffffffu, p1, sB);
            float f2 = __shfl_sync(0xffffffffu, p2, sB);
            float f3 = __shfl_sync(0xffffffffu, p3, sB);
            uint32_t a[4];
            a[0] = __float_as_uint(odd ? e1 : e0);
            a[1] = __float_as_uint(odd ? e3 : e2);
            a[2] = __float_as_uint(odd ? f1 : f0);
            a[3] = __float_as_uint(odd ? f3 : f2);
#pragma unroll
            for (int dt = 0; dt < 8; dt++) {
                uint32_t b[2];
                b[0] = __float_as_uint(Vb[(ks*8 + t    )*ST + dt*8 + gr]);
                b[1] = __float_as_uint(Vb[(ks*8 + t + 4)*ST + dt*8 + gr]);
                mma8(accO[dt], a, b);
            }
        }
        __syncthreads();
    }

    if (t == 0) {
        d_pstat[((size_t)sp * GG + g) * NN + n0 + row0] = make_float2(rmax0, rsum0);
        d_pstat[((size_t)sp * GG + g) * NN + n0 + row1] = make_float2(rmax1, rsum1);
    }
    float* po = d_po + (size_t)sp * NN * FEAT;
#pragma unroll
    for (int dt = 0; dt < 8; dt++) {
        int o = g*64 + dt*8 + 2*t;
        *(float2*)&po[(size_t)(n0 + row0) * FEAT + o] = make_float2(accO[dt][0], accO[dt][1]);
        *(float2*)&po[(size_t)(n0 + row1) * FEAT + o] = make_float2(accO[dt][2], accO[dt][3]);
    }
}

// ---------------- merge partials -> final output ----------------
__global__ __launch_bounds__(256)
void merge_kernel(const float* __restrict__ Wv_b, float* __restrict__ out)
{
    int idx = blockIdx.x * 256 + threadIdx.x;
    int n = idx >> 10, o = idx & 1023, g = o >> 6;
    float2 st[NSPLIT];
    float M = -1e30f;
#pragma unroll
    for (int s = 0; s < NSPLIT; s++) {
        st[s] = d_pstat[((size_t)s * GG + g) * NN + n];
        M = fmaxf(M, st[s].x);
    }
    float num = 0.0f, den = 0.0f;
#pragma unroll
    for (int s = 0; s < NSPLIT; s++) {
        float w = __expf(st[s].x - M);
        num += d_po[((size_t)s * NN + n) * FEAT + o] * w;
        den += st[s].y * w;
    }
    out[idx] = num / den + Wv_b[o];
}

// ---------------- launch ----------------
extern "C" void kernel_launch(void* const* d_in, const int* in_sizes, int n_in,
                              void* d_out, int out_size)
{
    const float* bbox     = (const float*)d_in[0];
    const float* ref_bbox = (const float*)d_in[1];
    const float* roi_feat = (const float*)d_in[2];
    const float* ref_feat = (const float*)d_in[3];
    const float* Wg_w     = (const float*)d_in[4];
    const float* Wg_b     = (const float*)d_in[5];
    const float* Wq_w     = (const float*)d_in[6];
    const float* Wq_b     = (const float*)d_in[7];
    const float* Wk_w     = (const float*)d_in[8];
    const float* Wk_b     = (const float*)d_in[9];
    const float* Wv_w     = (const float*)d_in[10];
    const float* Wv_b     = (const float*)d_in[11];
    const float* u        = (const float*)d_in[12];
    float* out = (float*)d_out;

    (void)in_sizes; (void)n_in; (void)out_size;

    static const int ATTN_SMEM = 2 * BUFSZ * 4;            // 73728 B
    static const int GEMM_SMEM = GSTAGES * STG_F * 4;      // 65536 B
    cudaFuncSetAttribute(attn_split_kernel, cudaFuncAttributeMaxDynamicSharedMemorySize, ATTN_SMEM);
    cudaFuncSetAttribute(megagemm, cudaFuncAttributeMaxDynamicSharedMemorySize, GEMM_SMEM);

    // Fork/join: w_kernel overlaps the GEMM chain on a side stream.
    cudaStream_t s1;
    cudaEvent_t evFork, evJoin;
    cudaStreamCreateWithFlags(&s1, cudaStreamNonBlocking);
    cudaEventCreateWithFlags(&evFork, cudaEventDisableTiming);
    cudaEventCreateWithFlags(&evJoin, cudaEventDisableTiming);

    prep_boxes_kernel<<<8, 256>>>(bbox, ref_bbox);
    cudaEventRecord(evFork, 0);
    cudaStreamWaitEvent(s1, evFork, 0);

    w_kernel<<<dim3(MM / 128, NN), 128, 0, s1>>>(Wg_w, Wg_b);
    cudaEventRecord(evJoin, s1);

    prep_tf32<<<2816, 256>>>(roi_feat, ref_feat, Wq_w, Wk_w, Wv_w);
    megagemm<<<288, 256, GEMM_SMEM>>>(Wq_b, Wk_b, u);

    cudaStreamWaitEvent(0, evJoin, 0);
    attn_split_kernel<<<dim3(NN / 64, GG, NSPLIT), 128, ATTN_SMEM>>>();
    merge_kernel<<<NN * FEAT / 256, 256>>>(Wv_b, out);
}